// round 10
// baseline (speedup 1.0000x reference)
#include <cuda_runtime.h>

#define BB 512
#define NN 128
#define DD 256
#define TT 512
#define NP (NN + 4)   // padded row stride for S (rows stay 16B aligned)
#define XP 68         // padded row stride for 64-wide tiles

typedef unsigned long long u64t;

#define FMA2(acc, a, b) \
    asm("fma.rn.f32x2 %0, %1, %2, %0;" : "+l"(acc) : "l"(a), "l"(b))
#define PACK2(out, v) \
    asm("mov.b64 %0, {%1, %1};" : "=l"(out) : "r"(__float_as_uint(v)))

__device__ __forceinline__ float lo32(u64t v) { return __uint_as_float((unsigned)v); }
__device__ __forceinline__ float hi32(u64t v) { return __uint_as_float((unsigned)(v >> 32)); }

struct Smem {
    float S[NN][NP];       // assignment matrix S           (67.6 KB)
    float X[NN][XP];       // streamed 128x64 tile / Y      (34.8 KB)
    float w[DD];
    float outv[NN];
    float dis[NN];
    float rfac[NN];        // mask * dis
    float tvec[NN];
    float alpha[NN];
    float colfac[NN];
    unsigned int bits[4];
    float cutv;
    int   kidx;
    int   nuniq;
};

__global__ __launch_bounds__(256, 2)
void graph_coarsen_kernel(const float* __restrict__ x,
                          const float* __restrict__ adj,
                          const int*   __restrict__ head,
                          const float* __restrict__ lw,
                          const float* __restrict__ bias,
                          float* __restrict__ emb,
                          float* __restrict__ nadj)
{
    extern __shared__ char smraw[];
    Smem& sm = *reinterpret_cast<Smem*>(smraw);

    const int b    = blockIdx.x;
    const int tid  = threadIdx.x;
    const int lane = tid & 31;
    const int wid  = tid >> 5;

    const float* adjB = adj + (size_t)b * NN * NN;
    const float* xB   = x   + (size_t)b * NN * DD;

    sm.w[tid] = lw[tid];  // DD == 256 == blockDim
    if (tid < 4) sm.bits[tid] = 0u;
    __syncthreads();

    // ---- out[n] = x[n,:] . w ----
    for (int n = wid; n < NN; n += 8) {
        const float* xr = xB + n * DD;
        float s = 0.f;
        #pragma unroll
        for (int t = 0; t < DD / 32; ++t)
            s = fmaf(xr[lane + 32 * t], sm.w[lane + 32 * t], s);
        #pragma unroll
        for (int o = 16; o > 0; o >>= 1) s += __shfl_down_sync(0xffffffffu, s, o);
        if (lane == 0) sm.outv[n] = s;
    }
    // ---- degree / dis / mask (adj from global, coalesced) ----
    for (int i = wid; i < NN; i += 8) {
        const float* ar = adjB + i * NN;
        float s = 0.f;
        #pragma unroll
        for (int t = 0; t < NN / 32; ++t) s += ar[lane + 32 * t];
        #pragma unroll
        for (int o = 16; o > 0; o >>= 1) s += __shfl_down_sync(0xffffffffu, s, o);
        if (lane == 0) {
            float deg = s + 1.0f;
            float dv  = rsqrtf(fmaxf(deg, 1.0f));
            sm.dis[i]  = dv;
            sm.rfac[i] = (s > 0.f) ? dv : 0.f;
        }
    }
    __syncthreads();

    if (tid < NN) sm.tvec[tid] = sm.dis[tid] * sm.outv[tid];
    {
        int v0 = head[(size_t)b * TT + tid];
        int v1 = head[(size_t)b * TT + 256 + tid];
        atomicOr(&sm.bits[v0 >> 5], 1u << (v0 & 31));
        atomicOr(&sm.bits[v1 >> 5], 1u << (v1 & 31));
    }
    __syncthreads();

    // ---- o2 = norm_adj @ out + bias ; alpha = sigmoid(o2^2) ----
    {
        const float biasv = bias[0];
        for (int i = wid; i < NN; i += 8) {
            const float* ar = adjB + i * NN;
            float s = 0.f;
            #pragma unroll
            for (int t = 0; t < NN / 32; ++t)
                s = fmaf(ar[lane + 32 * t], sm.tvec[lane + 32 * t], s);
            #pragma unroll
            for (int o = 16; o > 0; o >>= 1) s += __shfl_down_sync(0xffffffffu, s, o);
            if (lane == 0) {
                float o2 = fmaf(sm.rfac[i], s + sm.tvec[i], biasv);
                float q  = o2 * o2;
                sm.alpha[i] = 1.0f / (1.0f + expf(-q));
            }
        }
    }
    if (tid == 0) {
        int nu = __popc(sm.bits[0]) + __popc(sm.bits[1]) +
                 __popc(sm.bits[2]) + __popc(sm.bits[3]);
        sm.nuniq = nu;
        int k   = (int)ceilf((float)nu * 0.1f) + 1;
        int idx = k - 1;
        if (idx < 0) idx = 0;
        if (idx > NN - 1) idx = NN - 1;
        sm.kidx = idx;
    }
    __syncthreads();

    // ---- cut = k-th largest alpha (rank with stable tie-break) ----
    if (tid < NN) {
        float ai = sm.alpha[tid];
        int cnt = 0;
        #pragma unroll 8
        for (int j = 0; j < NN; ++j) {
            float aj = sm.alpha[j];
            cnt += (aj > ai) || (aj == ai && j < tid);
        }
        if (cnt == sm.kidx) sm.cutv = (sm.nuniq > 1) ? ai : 0.f;
    }
    __syncthreads();
    if (tid < NN) {
        float ca = fmaxf(sm.alpha[tid] + 1e-7f - sm.cutv, 0.f);
        sm.colfac[tid] = sm.dis[tid] * ca;
    }
    __syncthreads();

    // ---- build S: S[i,j] = rfac[i]*(adj+I)_ij*colfac[j], row-L1-normalized ----
    for (int i = wid; i < NN; i += 8) {
        const float* ar = adjB + i * NN;
        float v[NN / 32];
        float s = 0.f;
        #pragma unroll
        for (int t = 0; t < NN / 32; ++t) {
            int j = lane + 32 * t;
            float a = ar[j] + ((j == i) ? 1.f : 0.f);
            v[t] = a * sm.colfac[j];
            s += v[t];
        }
        #pragma unroll
        for (int o = 16; o > 0; o >>= 1) s += __shfl_down_sync(0xffffffffu, s, o);
        s = __shfl_sync(0xffffffffu, s, 0);
        float rf  = sm.rfac[i];
        float tot = rf * s;                       // L1 row sum (all nonneg)
        float r2  = rf / fmaxf(tot, 1e-12f);
        #pragma unroll
        for (int t = 0; t < NN / 32; ++t)
            sm.S[i][lane + 32 * t] = r2 * v[t];
    }
    __syncthreads();

    const int ty = tid >> 4, tx = tid & 15;
    const int i0 = ty * 8;
    const int koff = wid * 16;   // stagger k-start per warp (desync SMSP peers)

    // ---- GEMM1: emb = S^T @ x  (4 chunks of 64 d-cols through X) ----
    // A prefetch depth 1, B prefetch depth 2, warp-staggered k order.
    {
        float* embB = emb + (size_t)b * NN * DD;
        const int dd = tx * 4;
        for (int dc = 0; dc < 4; ++dc) {
            const int d0 = dc * 64;
            for (int idx = tid; idx < NN * 16; idx += 256) {
                int k = idx >> 4, c = (idx & 15) << 2;
                *reinterpret_cast<float4*>(&sm.X[k][c]) =
                    *reinterpret_cast<const float4*>(&xB[k * DD + d0 + c]);
            }
            __syncthreads();
            u64t acc[4][4];
            #pragma unroll
            for (int p = 0; p < 4; ++p)
                #pragma unroll
                for (int c = 0; c < 4; ++c) acc[p][c] = 0ull;

            ulonglong2 cA0 = *reinterpret_cast<ulonglong2*>(&sm.S[koff][i0]);
            ulonglong2 cA1 = *reinterpret_cast<ulonglong2*>(&sm.S[koff][i0 + 4]);
            float4     cB  = *reinterpret_cast<float4*>(&sm.X[koff][dd]);
            float4     mB  = *reinterpret_cast<float4*>(&sm.X[(koff + 1) & 127][dd]);
            #pragma unroll 4
            for (int kk = 0; kk < NN; ++kk) {
                int kp = (kk + koff + 1) & 127;
                int kb = (kk + koff + 2) & 127;
                ulonglong2 nA0 = *reinterpret_cast<ulonglong2*>(&sm.S[kp][i0]);
                ulonglong2 nA1 = *reinterpret_cast<ulonglong2*>(&sm.S[kp][i0 + 4]);
                float4     nB  = *reinterpret_cast<float4*>(&sm.X[kb][dd]);
                u64t Bp[4];
                PACK2(Bp[0], cB.x); PACK2(Bp[1], cB.y);
                PACK2(Bp[2], cB.z); PACK2(Bp[3], cB.w);
                u64t Ap[4] = {cA0.x, cA0.y, cA1.x, cA1.y};
                #pragma unroll
                for (int p = 0; p < 4; ++p)
                    #pragma unroll
                    for (int c = 0; c < 4; ++c)
                        FMA2(acc[p][c], Ap[p], Bp[c]);
                cA0 = nA0; cA1 = nA1; cB = mB; mB = nB;
            }
            #pragma unroll
            for (int p = 0; p < 4; ++p) {
                float4 v0 = {lo32(acc[p][0]), lo32(acc[p][1]), lo32(acc[p][2]), lo32(acc[p][3])};
                float4 v1 = {hi32(acc[p][0]), hi32(acc[p][1]), hi32(acc[p][2]), hi32(acc[p][3])};
                *reinterpret_cast<float4*>(&embB[(i0 + 2 * p)     * DD + d0 + dd]) = v0;
                *reinterpret_cast<float4*>(&embB[(i0 + 2 * p + 1) * DD + d0 + dd]) = v1;
            }
            __syncthreads();
        }
    }

    // ---- new_adj = S^T (adj S): per 64-col chunk, Y = adj@S_chunk into X,
    //      then nadj_chunk = S^T @ Y ----
    {
        float* nadjB = nadj + (size_t)b * NN * NN;
        const int jj = tx * 4;
        for (int jc = 0; jc < 2; ++jc) {
            const int j0 = jc * 64;

            // Y[i0..i0+7, jj..jj+3] = adj @ S[:, j0:j0+64]
            // adj LDGs batched at iter top (MLP 8-16), S pack prefetched.
            u64t accY[8][2];
            #pragma unroll
            for (int r = 0; r < 8; ++r) { accY[r][0] = 0ull; accY[r][1] = 0ull; }
            ulonglong2 cBk[4];
            #pragma unroll
            for (int kk = 0; kk < 4; ++kk)
                cBk[kk] = *reinterpret_cast<ulonglong2*>(&sm.S[kk][j0 + jj]);
            #pragma unroll 2
            for (int k4 = 0; k4 < NN; k4 += 4) {
                float4 av[8];
                #pragma unroll
                for (int r = 0; r < 8; ++r)
                    av[r] = *reinterpret_cast<const float4*>(&adjB[(i0 + r) * NN + k4]);
                ulonglong2 nBk[4];
                #pragma unroll
                for (int kk = 0; kk < 4; ++kk)
                    nBk[kk] = *reinterpret_cast<ulonglong2*>(&sm.S[k4 + 4 + kk][j0 + jj]);
                #pragma unroll
                for (int kk = 0; kk < 4; ++kk) {
                    #pragma unroll
                    for (int r = 0; r < 8; ++r) {
                        float as = (kk == 0) ? av[r].x : (kk == 1) ? av[r].y
                                 : (kk == 2) ? av[r].z : av[r].w;
                        u64t pa;
                        PACK2(pa, as);
                        FMA2(accY[r][0], pa, cBk[kk].x);
                        FMA2(accY[r][1], pa, cBk[kk].y);
                    }
                }
                #pragma unroll
                for (int kk = 0; kk < 4; ++kk) cBk[kk] = nBk[kk];
            }
            __syncthreads();   // previous readers of X are done
            #pragma unroll
            for (int r = 0; r < 8; ++r) {
                float4 v = {lo32(accY[r][0]), hi32(accY[r][0]),
                            lo32(accY[r][1]), hi32(accY[r][1])};
                *reinterpret_cast<float4*>(&sm.X[i0 + r][jj]) = v;
            }
            __syncthreads();

            // nadj[:, j0:j0+64] = S^T @ Y  (row-pair packed, depth-2 B, staggered)
            u64t acc[4][4];
            #pragma unroll
            for (int p = 0; p < 4; ++p)
                #pragma unroll
                for (int c = 0; c < 4; ++c) acc[p][c] = 0ull;
            ulonglong2 cA0 = *reinterpret_cast<ulonglong2*>(&sm.S[koff][i0]);
            ulonglong2 cA1 = *reinterpret_cast<ulonglong2*>(&sm.S[koff][i0 + 4]);
            float4     cB  = *reinterpret_cast<float4*>(&sm.X[koff][jj]);
            float4     mB  = *reinterpret_cast<float4*>(&sm.X[(koff + 1) & 127][jj]);
            #pragma unroll 4
            for (int kk = 0; kk < NN; ++kk) {
                int kp = (kk + koff + 1) & 127;
                int kb = (kk + koff + 2) & 127;
                ulonglong2 nA0 = *reinterpret_cast<ulonglong2*>(&sm.S[kp][i0]);
                ulonglong2 nA1 = *reinterpret_cast<ulonglong2*>(&sm.S[kp][i0 + 4]);
                float4     nB  = *reinterpret_cast<float4*>(&sm.X[kb][jj]);
                u64t Bp[4];
                PACK2(Bp[0], cB.x); PACK2(Bp[1], cB.y);
                PACK2(Bp[2], cB.z); PACK2(Bp[3], cB.w);
                u64t Ap[4] = {cA0.x, cA0.y, cA1.x, cA1.y};
                #pragma unroll
                for (int p = 0; p < 4; ++p)
                    #pragma unroll
                    for (int c = 0; c < 4; ++c)
                        FMA2(acc[p][c], Ap[p], Bp[c]);
                cA0 = nA0; cA1 = nA1; cB = mB; mB = nB;
            }
            #pragma unroll
            for (int p = 0; p < 4; ++p) {
                float4 v0 = {lo32(acc[p][0]), lo32(acc[p][1]), lo32(acc[p][2]), lo32(acc[p][3])};
                float4 v1 = {hi32(acc[p][0]), hi32(acc[p][1]), hi32(acc[p][2]), hi32(acc[p][3])};
                *reinterpret_cast<float4*>(&nadjB[(i0 + 2 * p)     * NN + j0 + jj]) = v0;
                *reinterpret_cast<float4*>(&nadjB[(i0 + 2 * p + 1) * NN + j0 + jj]) = v1;
            }
            __syncthreads();
        }
    }
}

extern "C" void kernel_launch(void* const* d_in, const int* in_sizes, int n_in,
                              void* d_out, int out_size) {
    const float* x    = (const float*)d_in[0];   // concept_hidden [B,N,D]
    const float* adj  = (const float*)d_in[1];   // adj [B,N,N]
    const int*   head = (const int*)d_in[2];     // head [B,T]
    const float* lw   = (const float*)d_in[3];   // lin_w [1,D]
    const float* bias = (const float*)d_in[4];   // bias [1]

    float* out  = (float*)d_out;
    float* emb  = out;                                  // [B,N,D]
    float* nadj = out + (size_t)BB * NN * DD;           // [B,N,N]

    const int smemBytes = (int)sizeof(Smem);
    cudaFuncSetAttribute(graph_coarsen_kernel,
                         cudaFuncAttributeMaxDynamicSharedMemorySize, smemBytes);
    graph_coarsen_kernel<<<BB, 256, smemBytes>>>(x, adj, head, lw, bias, emb, nadj);
}

// round 14
// speedup vs baseline: 1.1067x; 1.1067x over previous
#include <cuda_runtime.h>

#define BB 512
#define NN 128
#define DD 256
#define TT 512
#define NP (NN + 4)   // padded row stride for S
#define XP 68         // padded row stride for 64-wide tiles

typedef unsigned int u32t;

struct Smem {
    float S[NN][NP];       // assignment matrix S           (67.6 KB)
    float X[NN][XP];       // staged x/adj chunk, then Zc   (34.8 KB)
    float w[DD];
    float outv[NN];
    float dis[NN];
    float rfac[NN];
    float tvec[NN];
    float alpha[NN];
    float colfac[NN];
    unsigned int bits[4];
    float cutv;
    int   kidx;
    int   nuniq;
};

// split fp32 into tf32 hi + tf32 lo (v ~= hi + lo, residual ~2^-22)
__device__ __forceinline__ void split_tf32(float v, u32t& hi, u32t& lo) {
    u32t h, l;
    asm("cvt.rna.tf32.f32 %0, %1;" : "=r"(h) : "f"(v));
    float rem = v - __uint_as_float(h);
    asm("cvt.rna.tf32.f32 %0, %1;" : "=r"(l) : "f"(rem));
    hi = h; lo = l;
}

__device__ __forceinline__ void mma8(float& d0, float& d1, float& d2, float& d3,
                                     u32t a0, u32t a1, u32t a2, u32t a3,
                                     u32t b0, u32t b1) {
    asm volatile("mma.sync.aligned.m16n8k8.row.col.f32.tf32.tf32.f32 "
        "{%0,%1,%2,%3}, {%4,%5,%6,%7}, {%8,%9}, {%0,%1,%2,%3};"
        : "+f"(d0), "+f"(d1), "+f"(d2), "+f"(d3)
        : "r"(a0), "r"(a1), "r"(a2), "r"(a3), "r"(b0), "r"(b1));
}

__global__ __launch_bounds__(256, 2)
void graph_coarsen_kernel(const float* __restrict__ x,
                          const float* __restrict__ adj,
                          const int*   __restrict__ head,
                          const float* __restrict__ lw,
                          const float* __restrict__ bias,
                          float* __restrict__ emb,
                          float* __restrict__ nadj)
{
    extern __shared__ char smraw[];
    Smem& sm = *reinterpret_cast<Smem*>(smraw);

    const int b    = blockIdx.x;
    const int tid  = threadIdx.x;
    const int lane = tid & 31;
    const int wid  = tid >> 5;

    const float* adjB = adj + (size_t)b * NN * NN;
    const float* xB   = x   + (size_t)b * NN * DD;

    sm.w[tid] = lw[tid];  // DD == 256 == blockDim
    if (tid < 4) sm.bits[tid] = 0u;
    __syncthreads();

    // ---- out[n] = x[n,:] . w ----
    for (int n = wid; n < NN; n += 8) {
        const float* xr = xB + n * DD;
        float s = 0.f;
        #pragma unroll
        for (int t = 0; t < DD / 32; ++t)
            s = fmaf(xr[lane + 32 * t], sm.w[lane + 32 * t], s);
        #pragma unroll
        for (int o = 16; o > 0; o >>= 1) s += __shfl_down_sync(0xffffffffu, s, o);
        if (lane == 0) sm.outv[n] = s;
    }
    // ---- degree / dis / mask ----
    for (int i = wid; i < NN; i += 8) {
        const float* ar = adjB + i * NN;
        float s = 0.f;
        #pragma unroll
        for (int t = 0; t < NN / 32; ++t) s += ar[lane + 32 * t];
        #pragma unroll
        for (int o = 16; o > 0; o >>= 1) s += __shfl_down_sync(0xffffffffu, s, o);
        if (lane == 0) {
            float deg = s + 1.0f;
            float dv  = rsqrtf(fmaxf(deg, 1.0f));
            sm.dis[i]  = dv;
            sm.rfac[i] = (s > 0.f) ? dv : 0.f;
        }
    }
    __syncthreads();

    if (tid < NN) sm.tvec[tid] = sm.dis[tid] * sm.outv[tid];
    {
        int v0 = head[(size_t)b * TT + tid];
        int v1 = head[(size_t)b * TT + 256 + tid];
        atomicOr(&sm.bits[v0 >> 5], 1u << (v0 & 31));
        atomicOr(&sm.bits[v1 >> 5], 1u << (v1 & 31));
    }
    __syncthreads();

    // ---- o2 = norm_adj @ out + bias ; alpha = sigmoid(o2^2) ----
    {
        const float biasv = bias[0];
        for (int i = wid; i < NN; i += 8) {
            const float* ar = adjB + i * NN;
            float s = 0.f;
            #pragma unroll
            for (int t = 0; t < NN / 32; ++t)
                s = fmaf(ar[lane + 32 * t], sm.tvec[lane + 32 * t], s);
            #pragma unroll
            for (int o = 16; o > 0; o >>= 1) s += __shfl_down_sync(0xffffffffu, s, o);
            if (lane == 0) {
                float o2 = fmaf(sm.rfac[i], s + sm.tvec[i], biasv);
                float q  = o2 * o2;
                sm.alpha[i] = 1.0f / (1.0f + expf(-q));
            }
        }
    }
    if (tid == 0) {
        int nu = __popc(sm.bits[0]) + __popc(sm.bits[1]) +
                 __popc(sm.bits[2]) + __popc(sm.bits[3]);
        sm.nuniq = nu;
        int k   = (int)ceilf((float)nu * 0.1f) + 1;
        int idx = k - 1;
        if (idx < 0) idx = 0;
        if (idx > NN - 1) idx = NN - 1;
        sm.kidx = idx;
    }
    __syncthreads();

    // ---- cut = k-th largest alpha ----
    if (tid < NN) {
        float ai = sm.alpha[tid];
        int cnt = 0;
        #pragma unroll 8
        for (int j = 0; j < NN; ++j) {
            float aj = sm.alpha[j];
            cnt += (aj > ai) || (aj == ai && j < tid);
        }
        if (cnt == sm.kidx) sm.cutv = (sm.nuniq > 1) ? ai : 0.f;
    }
    __syncthreads();
    if (tid < NN) {
        float ca = fmaxf(sm.alpha[tid] + 1e-7f - sm.cutv, 0.f);
        sm.colfac[tid] = sm.dis[tid] * ca;
    }
    __syncthreads();

    // ---- build S ----
    for (int i = wid; i < NN; i += 8) {
        const float* ar = adjB + i * NN;
        float v[NN / 32];
        float s = 0.f;
        #pragma unroll
        for (int t = 0; t < NN / 32; ++t) {
            int j = lane + 32 * t;
            float a = ar[j] + ((j == i) ? 1.f : 0.f);
            v[t] = a * sm.colfac[j];
            s += v[t];
        }
        #pragma unroll
        for (int o = 16; o > 0; o >>= 1) s += __shfl_down_sync(0xffffffffu, s, o);
        s = __shfl_sync(0xffffffffu, s, 0);
        float rf  = sm.rfac[i];
        float tot = rf * s;
        float r2  = rf / fmaxf(tot, 1e-12f);
        #pragma unroll
        for (int t = 0; t < NN / 32; ++t)
            sm.S[i][lane + 32 * t] = r2 * v[t];
    }
    __syncthreads();

    // ---- mma fragment coords ----
    const int r8 = lane >> 2;        // 0..7  (row / n-col within tile)
    const int c4 = lane & 3;         // 0..3  (k within tile)
    const int m0 = wid * 16;         // warp's 16-row M strip

    // ================= GEMM1: emb = S^T @ x (4 chunks of 64 d-cols) ============
    {
        float* embB = emb + (size_t)b * NN * DD;
        for (int dc = 0; dc < 4; ++dc) {
            const int d0 = dc * 64;
            __syncthreads();   // previous chunk's X readers done
            for (int idx = tid; idx < NN * 16; idx += 256) {
                int k = idx >> 4, cc = (idx & 15) << 2;
                *reinterpret_cast<float4*>(&sm.X[k][cc]) =
                    *reinterpret_cast<const float4*>(&xB[k * DD + d0 + cc]);
            }
            __syncthreads();

            float C[8][4];
            #pragma unroll
            for (int nt = 0; nt < 8; ++nt)
                #pragma unroll
                for (int q = 0; q < 4; ++q) C[nt][q] = 0.f;

            for (int k8 = 0; k8 < 16; ++k8) {
                const int k0 = k8 * 8;
                // A[m,k] = S^T[m,k] = S[k][m]
                float a0 = sm.S[k0 + c4][m0 + r8];
                float a1 = sm.S[k0 + c4][m0 + r8 + 8];
                float a2 = sm.S[k0 + c4 + 4][m0 + r8];
                float a3 = sm.S[k0 + c4 + 4][m0 + r8 + 8];
                u32t Ah[4], Al[4];
                split_tf32(a0, Ah[0], Al[0]); split_tf32(a1, Ah[1], Al[1]);
                split_tf32(a2, Ah[2], Al[2]); split_tf32(a3, Ah[3], Al[3]);
                #pragma unroll
                for (int nt = 0; nt < 8; ++nt) {
                    float b0 = sm.X[k0 + c4][nt * 8 + r8];
                    float b1 = sm.X[k0 + 4 + c4][nt * 8 + r8];
                    u32t Bh0, Bl0, Bh1, Bl1;
                    split_tf32(b0, Bh0, Bl0); split_tf32(b1, Bh1, Bl1);
                    mma8(C[nt][0], C[nt][1], C[nt][2], C[nt][3],
                         Ah[0], Ah[1], Ah[2], Ah[3], Bh0, Bh1);
                    mma8(C[nt][0], C[nt][1], C[nt][2], C[nt][3],
                         Al[0], Al[1], Al[2], Al[3], Bh0, Bh1);
                    mma8(C[nt][0], C[nt][1], C[nt][2], C[nt][3],
                         Ah[0], Ah[1], Ah[2], Ah[3], Bl0, Bl1);
                }
            }
            #pragma unroll
            for (int nt = 0; nt < 8; ++nt) {
                int col = d0 + nt * 8 + 2 * c4;
                float2 v0 = {C[nt][0], C[nt][1]};
                float2 v1 = {C[nt][2], C[nt][3]};
                *reinterpret_cast<float2*>(&embB[(m0 + r8) * DD + col])     = v0;
                *reinterpret_cast<float2*>(&embB[(m0 + r8 + 8) * DD + col]) = v1;
            }
        }
    }

    // ================= nadj = S^T adj S, K split in two 64-chunks ==============
    {
        float* nadjB = nadj + (size_t)b * NN * NN;
        for (int c = 0; c < 2; ++c) {
            const int ck = c * 64;
            __syncthreads();   // prior X readers done
            for (int idx = tid; idx < NN * 16; idx += 256) {
                int k = idx >> 4, cc = (idx & 15) << 2;
                *reinterpret_cast<float4*>(&sm.X[k][cc]) =
                    *reinterpret_cast<const float4*>(&adjB[k * NN + ck + cc]);
            }
            __syncthreads();

            // ---- Zc = S^T @ adj[:, ck:ck+64]  (warp strip 16 x 64 in regs) ----
            float Z[8][4];
            #pragma unroll
            for (int nt = 0; nt < 8; ++nt)
                #pragma unroll
                for (int q = 0; q < 4; ++q) Z[nt][q] = 0.f;
            for (int k8 = 0; k8 < 16; ++k8) {
                const int k0 = k8 * 8;
                float a0 = sm.S[k0 + c4][m0 + r8];
                float a1 = sm.S[k0 + c4][m0 + r8 + 8];
                float a2 = sm.S[k0 + c4 + 4][m0 + r8];
                float a3 = sm.S[k0 + c4 + 4][m0 + r8 + 8];
                u32t Ah[4], Al[4];
                split_tf32(a0, Ah[0], Al[0]); split_tf32(a1, Ah[1], Al[1]);
                split_tf32(a2, Ah[2], Al[2]); split_tf32(a3, Ah[3], Al[3]);
                #pragma unroll
                for (int nt = 0; nt < 8; ++nt) {
                    float b0 = sm.X[k0 + c4][nt * 8 + r8];
                    float b1 = sm.X[k0 + 4 + c4][nt * 8 + r8];
                    u32t Bh0, Bl0, Bh1, Bl1;
                    split_tf32(b0, Bh0, Bl0); split_tf32(b1, Bh1, Bl1);
                    mma8(Z[nt][0], Z[nt][1], Z[nt][2], Z[nt][3],
                         Ah[0], Ah[1], Ah[2], Ah[3], Bh0, Bh1);
                    mma8(Z[nt][0], Z[nt][1], Z[nt][2], Z[nt][3],
                         Al[0], Al[1], Al[2], Al[3], Bh0, Bh1);
                    mma8(Z[nt][0], Z[nt][1], Z[nt][2], Z[nt][3],
                         Ah[0], Ah[1], Ah[2], Ah[3], Bl0, Bl1);
                }
            }
            __syncthreads();   // everyone done reading adj chunk from X

            // store Zc into X rows m0..m0+15 (warp-private rows)
            #pragma unroll
            for (int nt = 0; nt < 8; ++nt) {
                int col = nt * 8 + 2 * c4;
                float2 v0 = {Z[nt][0], Z[nt][1]};
                float2 v1 = {Z[nt][2], Z[nt][3]};
                *reinterpret_cast<float2*>(&sm.X[m0 + r8][col])     = v0;
                *reinterpret_cast<float2*>(&sm.X[m0 + r8 + 8][col]) = v1;
            }
            __syncwarp();

            // ---- partial nadj strip: P = Zc @ S[ck:ck+64, :]  (16 x 128) ----
            float P[16][4];
            #pragma unroll
            for (int nt = 0; nt < 16; ++nt)
                #pragma unroll
                for (int q = 0; q < 4; ++q) P[nt][q] = 0.f;
            for (int k8 = 0; k8 < 8; ++k8) {
                const int k0 = k8 * 8;
                // A[m,k] = Zc[m][k] = X[m][k]  (row-major)
                float a0 = sm.X[m0 + r8][k0 + c4];
                float a1 = sm.X[m0 + r8 + 8][k0 + c4];
                float a2 = sm.X[m0 + r8][k0 + c4 + 4];
                float a3 = sm.X[m0 + r8 + 8][k0 + c4 + 4];
                u32t Ah[4], Al[4];
                split_tf32(a0, Ah[0], Al[0]); split_tf32(a1, Ah[1], Al[1]);
                split_tf32(a2, Ah[2], Al[2]); split_tf32(a3, Ah[3], Al[3]);
                #pragma unroll
                for (int nt = 0; nt < 16; ++nt) {
                    float b0 = sm.S[ck + k0 + c4][nt * 8 + r8];
                    float b1 = sm.S[ck + k0 + 4 + c4][nt * 8 + r8];
                    u32t Bh0, Bl0, Bh1, Bl1;
                    split_tf32(b0, Bh0, Bl0); split_tf32(b1, Bh1, Bl1);
                    mma8(P[nt][0], P[nt][1], P[nt][2], P[nt][3],
                         Ah[0], Ah[1], Ah[2], Ah[3], Bh0, Bh1);
                    mma8(P[nt][0], P[nt][1], P[nt][2], P[nt][3],
                         Al[0], Al[1], Al[2], Al[3], Bh0, Bh1);
                    mma8(P[nt][0], P[nt][1], P[nt][2], P[nt][3],
                         Ah[0], Ah[1], Ah[2], Ah[3], Bl0, Bl1);
                }
            }
            // write (c==0) or accumulate (c==1) into nadj
            #pragma unroll
            for (int nt = 0; nt < 16; ++nt) {
                int col = nt * 8 + 2 * c4;
                float* p0 = &nadjB[(m0 + r8) * NN + col];
                float* p1 = &nadjB[(m0 + r8 + 8) * NN + col];
                if (c == 0) {
                    *reinterpret_cast<float2*>(p0) = make_float2(P[nt][0], P[nt][1]);
                    *reinterpret_cast<float2*>(p1) = make_float2(P[nt][2], P[nt][3]);
                } else {
                    float2 o0 = *reinterpret_cast<float2*>(p0);
                    float2 o1 = *reinterpret_cast<float2*>(p1);
                    *reinterpret_cast<float2*>(p0) =
                        make_float2(o0.x + P[nt][0], o0.y + P[nt][1]);
                    *reinterpret_cast<float2*>(p1) =
                        make_float2(o1.x + P[nt][2], o1.y + P[nt][3]);
                }
            }
        }
    }
}

extern "C" void kernel_launch(void* const* d_in, const int* in_sizes, int n_in,
                              void* d_out, int out_size) {
    const float* x    = (const float*)d_in[0];   // concept_hidden [B,N,D]
    const float* adj  = (const float*)d_in[1];   // adj [B,N,N]
    const int*   head = (const int*)d_in[2];     // head [B,T]
    const float* lw   = (const float*)d_in[3];   // lin_w [1,D]
    const float* bias = (const float*)d_in[4];   // bias [1]

    float* out  = (float*)d_out;
    float* emb  = out;                                  // [B,N,D]
    float* nadj = out + (size_t)BB * NN * DD;           // [B,N,N]

    const int smemBytes = (int)sizeof(Smem);
    cudaFuncSetAttribute(graph_coarsen_kernel,
                         cudaFuncAttributeMaxDynamicSharedMemorySize, smemBytes);
    graph_coarsen_kernel<<<BB, 256, smemBytes>>>(x, adj, head, lw, bias, emb, nadj);
}